// round 2
// baseline (speedup 1.0000x reference)
#include <cuda_runtime.h>

#define N_NODES 100000
#define D_FEAT 32

// Scratch (no cudaMalloc allowed): degree counters, per-node norm, prescaled features.
__device__ int   g_deg[N_NODES];
__device__ float g_norm[N_NODES];
__device__ float g_x[N_NODES * D_FEAT];

// ---------------------------------------------------------------------------
// Kernel 1: zero degree counters and output buffer (d_out is poisoned 0xAA).
// ---------------------------------------------------------------------------
__global__ void k_zero(float* __restrict__ out, int n_nodes)
{
    int i = blockIdx.x * blockDim.x + threadIdx.x;
    int total = n_nodes * D_FEAT;
    if (i < total) out[i] = 0.0f;
    if (i < n_nodes) g_deg[i] = 0;
}

// ---------------------------------------------------------------------------
// Kernel 2: out-degree of src.  1.6M int RED.ADDs across 100k counters.
// ---------------------------------------------------------------------------
__global__ void k_degree(const int* __restrict__ src, int n_edges)
{
    int i = blockIdx.x * blockDim.x + threadIdx.x;
    if (i < n_edges) {
        atomicAdd(&g_deg[src[i]], 1);
    }
}

// ---------------------------------------------------------------------------
// Kernel 3: norm = deg>0 ? rsqrt(deg) : 0 ; prescale x = features * norm.
// ---------------------------------------------------------------------------
__global__ void k_prescale(const float* __restrict__ features, int n_nodes)
{
    int i = blockIdx.x * blockDim.x + threadIdx.x;
    int total = n_nodes * D_FEAT;
    if (i >= total) return;
    int n = i >> 5;          // D_FEAT == 32
    int d = i & 31;
    int deg = __ldg(&g_deg[n]);
    float norm = (deg > 0) ? rsqrtf((float)deg) : 0.0f;
    if (d == 0) g_norm[n] = norm;
    g_x[i] = features[i] * norm;
}

// ---------------------------------------------------------------------------
// Kernel 4: edge scatter.  One warp per edge: coalesced 128B read of x[src],
// coalesced 32-lane RED.ADD into out[dst].
// ---------------------------------------------------------------------------
__global__ void k_scatter(const int* __restrict__ src,
                          const int* __restrict__ dst,
                          float* __restrict__ out, int n_edges)
{
    int gtid = blockIdx.x * blockDim.x + threadIdx.x;
    int e    = gtid >> 5;
    int lane = gtid & 31;
    if (e >= n_edges) return;
    int s = __ldg(&src[e]);
    int t = __ldg(&dst[e]);
    float v = __ldg(&g_x[s * D_FEAT + lane]);
    atomicAdd(&out[t * D_FEAT + lane], v);
}

// ---------------------------------------------------------------------------
// Kernel 5: post-scale by destination norm.
// ---------------------------------------------------------------------------
__global__ void k_postscale(float* __restrict__ out, int n_nodes)
{
    int i = blockIdx.x * blockDim.x + threadIdx.x;
    int total = n_nodes * D_FEAT;
    if (i >= total) return;
    out[i] *= __ldg(&g_norm[i >> 5]);
}

extern "C" void kernel_launch(void* const* d_in, const int* in_sizes, int n_in,
                              void* d_out, int out_size)
{
    const float* features = (const float*)d_in[0];
    const int*   src      = (const int*)d_in[1];
    const int*   dst      = (const int*)d_in[2];
    float*       out      = (float*)d_out;

    int n_nodes = in_sizes[0] / D_FEAT;   // 100000
    int n_edges = in_sizes[1];            // 1600000

    int total_nd = n_nodes * D_FEAT;
    const int TPB = 256;

    k_zero<<<(total_nd + TPB - 1) / TPB, TPB>>>(out, n_nodes);
    k_degree<<<(n_edges + TPB - 1) / TPB, TPB>>>(src, n_edges);
    k_prescale<<<(total_nd + TPB - 1) / TPB, TPB>>>(features, n_nodes);

    long long scatter_threads = (long long)n_edges * 32;
    int scatter_blocks = (int)((scatter_threads + TPB - 1) / TPB);
    k_scatter<<<scatter_blocks, TPB>>>(src, dst, out, n_edges);

    k_postscale<<<(total_nd + TPB - 1) / TPB, TPB>>>(out, n_nodes);
}

// round 3
// speedup vs baseline: 2.1488x; 2.1488x over previous
#include <cuda_runtime.h>

#define N_NODES 100000
#define D_FEAT 32
#define EDGES_PER_WARP 8

// Scratch (no cudaMalloc allowed)
__device__ int   g_deg[N_NODES];
__device__ float g_norm[N_NODES];

// ---------------------------------------------------------------------------
// Kernel 1: zero output (float4-vectorized) and degree counters.
// ---------------------------------------------------------------------------
__global__ void k_zero(float4* __restrict__ out4, int n_nodes)
{
    int i = blockIdx.x * blockDim.x + threadIdx.x;
    int total4 = n_nodes * (D_FEAT / 4);
    if (i < total4) out4[i] = make_float4(0.f, 0.f, 0.f, 0.f);
    if (i < n_nodes) g_deg[i] = 0;
}

// ---------------------------------------------------------------------------
// Kernel 2: out-degree of src.  int4-vectorized index reads.
// ---------------------------------------------------------------------------
__global__ void k_degree(const int4* __restrict__ src4, int n_edges4)
{
    int i = blockIdx.x * blockDim.x + threadIdx.x;
    if (i < n_edges4) {
        int4 s = __ldg(&src4[i]);
        atomicAdd(&g_deg[s.x], 1);
        atomicAdd(&g_deg[s.y], 1);
        atomicAdd(&g_deg[s.z], 1);
        atomicAdd(&g_deg[s.w], 1);
    }
}

// ---------------------------------------------------------------------------
// Kernel 3: norm = deg>0 ? rsqrt(deg) : 0   (tiny, 100k threads)
// ---------------------------------------------------------------------------
__global__ void k_norm(int n_nodes)
{
    int i = blockIdx.x * blockDim.x + threadIdx.x;
    if (i >= n_nodes) return;
    int deg = g_deg[i];
    g_norm[i] = (deg > 0) ? rsqrtf((float)deg) : 0.0f;
}

// ---------------------------------------------------------------------------
// Kernel 4: fused scatter.  Each warp handles EDGES_PER_WARP edges:
//   batch the independent index loads, then the independent coalesced 128B
//   feature reads (scaled by norm[s]*norm[t]), then the 32-lane RED.ADDs.
// This gives per-warp MLP ~ EDGES_PER_WARP instead of 1.
// ---------------------------------------------------------------------------
__global__ void k_scatter(const int*   __restrict__ src,
                          const int*   __restrict__ dst,
                          const float* __restrict__ feat,
                          float*       __restrict__ out, int n_edges)
{
    const int E = EDGES_PER_WARP;
    int gtid = blockIdx.x * blockDim.x + threadIdx.x;
    int warp = gtid >> 5;
    int lane = gtid & 31;
    int base = warp * E;
    if (base >= n_edges) return;

    int s[E], t[E];
    float v[E];

    if (base + E <= n_edges) {
        // fast path: full batch
        #pragma unroll
        for (int i = 0; i < E; i++) {
            s[i] = __ldg(&src[base + i]);
            t[i] = __ldg(&dst[base + i]);
        }
        #pragma unroll
        for (int i = 0; i < E; i++) {
            float w = __ldg(&g_norm[s[i]]) * __ldg(&g_norm[t[i]]);
            v[i] = __ldg(&feat[s[i] * D_FEAT + lane]) * w;
        }
        #pragma unroll
        for (int i = 0; i < E; i++)
            atomicAdd(&out[t[i] * D_FEAT + lane], v[i]);
    } else {
        int cnt = n_edges - base;
        for (int i = 0; i < cnt; i++) {
            int ss = __ldg(&src[base + i]);
            int tt = __ldg(&dst[base + i]);
            float w = __ldg(&g_norm[ss]) * __ldg(&g_norm[tt]);
            float vv = __ldg(&feat[ss * D_FEAT + lane]) * w;
            atomicAdd(&out[tt * D_FEAT + lane], vv);
        }
    }
}

extern "C" void kernel_launch(void* const* d_in, const int* in_sizes, int n_in,
                              void* d_out, int out_size)
{
    const float* features = (const float*)d_in[0];
    const int*   src      = (const int*)d_in[1];
    const int*   dst      = (const int*)d_in[2];
    float*       out      = (float*)d_out;

    int n_nodes = in_sizes[0] / D_FEAT;   // 100000
    int n_edges = in_sizes[1];            // 1600000

    const int TPB = 256;

    int total4 = n_nodes * (D_FEAT / 4);
    k_zero<<<(total4 + TPB - 1) / TPB, TPB>>>((float4*)out, n_nodes);

    int n_edges4 = n_edges / 4;           // 1.6M divisible by 4
    k_degree<<<(n_edges4 + TPB - 1) / TPB, TPB>>>((const int4*)src, n_edges4);

    k_norm<<<(n_nodes + TPB - 1) / TPB, TPB>>>(n_nodes);

    int warps = (n_edges + EDGES_PER_WARP - 1) / EDGES_PER_WARP;
    long long threads = (long long)warps * 32;
    int blocks = (int)((threads + TPB - 1) / TPB);
    k_scatter<<<blocks, TPB>>>(src, dst, features, out, n_edges);
}

// round 4
// speedup vs baseline: 2.2165x; 1.0315x over previous
#include <cuda_runtime.h>

#define N_NODES 100000
#define D_FEAT 32
#define EPW 8            // edges per warp (2 quads of 4)

// Scratch (no cudaMalloc allowed)
__device__ int   g_deg[N_NODES];
__device__ float g_norm[N_NODES];

// ---------------------------------------------------------------------------
// Kernel 1: zero output (float4) and degree counters.
// ---------------------------------------------------------------------------
__global__ void k_zero(float4* __restrict__ out4, int n_nodes)
{
    int i = blockIdx.x * blockDim.x + threadIdx.x;
    int total4 = n_nodes * (D_FEAT / 4);
    if (i < total4) out4[i] = make_float4(0.f, 0.f, 0.f, 0.f);
    if (i < n_nodes) g_deg[i] = 0;
}

// ---------------------------------------------------------------------------
// Kernel 2: out-degree of src (int4-vectorized reads).
// ---------------------------------------------------------------------------
__global__ void k_degree(const int4* __restrict__ src4, int n_edges4)
{
    int i = blockIdx.x * blockDim.x + threadIdx.x;
    if (i < n_edges4) {
        int4 s = __ldg(&src4[i]);
        atomicAdd(&g_deg[s.x], 1);
        atomicAdd(&g_deg[s.y], 1);
        atomicAdd(&g_deg[s.z], 1);
        atomicAdd(&g_deg[s.w], 1);
    }
}

// ---------------------------------------------------------------------------
// Kernel 3: norm = deg>0 ? rsqrt(deg) : 0
// ---------------------------------------------------------------------------
__global__ void k_norm(int n_nodes)
{
    int i = blockIdx.x * blockDim.x + threadIdx.x;
    if (i >= n_nodes) return;
    int deg = g_deg[i];
    g_norm[i] = (deg > 0) ? rsqrtf((float)deg) : 0.0f;
}

// ---------------------------------------------------------------------------
// 16-byte vector reduction (sm_90+): one RED wavefront instead of four.
// ---------------------------------------------------------------------------
__device__ __forceinline__ void red_add_v4(float4* addr, float4 v)
{
    asm volatile("red.global.add.v4.f32 [%0], {%1, %2, %3, %4};"
                 :: "l"(addr), "f"(v.x), "f"(v.y), "f"(v.z), "f"(v.w)
                 : "memory");
}

// ---------------------------------------------------------------------------
// Kernel 4: fused scatter.  Warp = 4 edge-groups of 8 lanes; each group
// handles one edge per quad-iteration with a single LDG.128 + RED.128 per
// lane.  8 edges per warp total, loads batched before REDs for MLP.
//   out[dst] += feat[src] * norm[src] * norm[dst]
// ---------------------------------------------------------------------------
__global__ void k_scatter(const int*    __restrict__ src,
                          const int*    __restrict__ dst,
                          const float4* __restrict__ feat4,
                          float4*       __restrict__ out4, int n_edges)
{
    const int Q = EPW / 4;                 // quads per warp
    int gtid = blockIdx.x * blockDim.x + threadIdx.x;
    int warp = gtid >> 5;
    int lane = gtid & 31;
    int grp  = lane >> 3;                  // edge within quad (0..3)
    int c    = lane & 7;                   // float4 chunk     (0..7)
    int base = warp * EPW;
    if (base >= n_edges) return;

    int    s[Q], t[Q];
    float4 v[Q];
    bool   ok[Q];

    #pragma unroll
    for (int q = 0; q < Q; q++) {
        int e = base + q * 4 + grp;
        ok[q] = (e < n_edges);
        int ec = ok[q] ? e : 0;
        s[q] = __ldg(&src[ec]);            // 8-lane broadcast
        t[q] = __ldg(&dst[ec]);
    }
    #pragma unroll
    for (int q = 0; q < Q; q++) {
        float w = __ldg(&g_norm[s[q]]) * __ldg(&g_norm[t[q]]);
        float4 f = __ldg(&feat4[s[q] * (D_FEAT / 4) + c]);
        v[q] = make_float4(f.x * w, f.y * w, f.z * w, f.w * w);
    }
    #pragma unroll
    for (int q = 0; q < Q; q++) {
        if (ok[q])
            red_add_v4(&out4[t[q] * (D_FEAT / 4) + c], v[q]);
    }
}

extern "C" void kernel_launch(void* const* d_in, const int* in_sizes, int n_in,
                              void* d_out, int out_size)
{
    const float* features = (const float*)d_in[0];
    const int*   src      = (const int*)d_in[1];
    const int*   dst      = (const int*)d_in[2];
    float*       out      = (float*)d_out;

    int n_nodes = in_sizes[0] / D_FEAT;   // 100000
    int n_edges = in_sizes[1];            // 1600000

    const int TPB = 256;

    int total4 = n_nodes * (D_FEAT / 4);
    k_zero<<<(total4 + TPB - 1) / TPB, TPB>>>((float4*)out, n_nodes);

    int n_edges4 = n_edges / 4;
    k_degree<<<(n_edges4 + TPB - 1) / TPB, TPB>>>((const int4*)src, n_edges4);

    k_norm<<<(n_nodes + TPB - 1) / TPB, TPB>>>(n_nodes);

    int warps = (n_edges + EPW - 1) / EPW;
    long long threads = (long long)warps * 32;
    int blocks = (int)((threads + TPB - 1) / TPB);
    k_scatter<<<blocks, TPB>>>(src, dst, (const float4*)features,
                               (float4*)out, n_edges);
}

// round 5
// speedup vs baseline: 2.3161x; 1.0449x over previous
#include <cuda_runtime.h>

#define N_NODES 100000
#define D_FEAT 32
#define EPW 16           // edges per warp (4 quads of 4)

// Scratch (no cudaMalloc allowed)
__device__ int    g_deg[N_NODES];
__device__ float  g_norm[N_NODES];
__device__ float4 g_x4[N_NODES * (D_FEAT / 4)];   // prescaled features

// ---------------------------------------------------------------------------
// Kernel 1: zero output (float4) and degree counters.
// ---------------------------------------------------------------------------
__global__ void k_zero(float4* __restrict__ out4, int n_nodes)
{
    int i = blockIdx.x * blockDim.x + threadIdx.x;
    int total4 = n_nodes * (D_FEAT / 4);
    if (i < total4) out4[i] = make_float4(0.f, 0.f, 0.f, 0.f);
    if (i < n_nodes) g_deg[i] = 0;
}

// ---------------------------------------------------------------------------
// Kernel 2: out-degree of src (int4-vectorized reads).
// ---------------------------------------------------------------------------
__global__ void k_degree(const int4* __restrict__ src4, int n_edges4)
{
    int i = blockIdx.x * blockDim.x + threadIdx.x;
    if (i < n_edges4) {
        int4 s = __ldg(&src4[i]);
        atomicAdd(&g_deg[s.x], 1);
        atomicAdd(&g_deg[s.y], 1);
        atomicAdd(&g_deg[s.z], 1);
        atomicAdd(&g_deg[s.w], 1);
    }
}

// ---------------------------------------------------------------------------
// Kernel 3: norm = deg>0 ? rsqrt(deg) : 0, and prescale x = feat * norm.
// One thread per float4 chunk (800k threads); norm computed redundantly per
// chunk (broadcast L1 hit), lane chunk 0 stores g_norm.
// ---------------------------------------------------------------------------
__global__ void k_prescale(const float4* __restrict__ feat4, int n_nodes)
{
    int i = blockIdx.x * blockDim.x + threadIdx.x;
    int total4 = n_nodes * (D_FEAT / 4);
    if (i >= total4) return;
    int n = i >> 3;                 // D_FEAT/4 == 8
    int deg = __ldg(&g_deg[n]);
    float norm = (deg > 0) ? rsqrtf((float)deg) : 0.0f;
    if ((i & 7) == 0) g_norm[n] = norm;
    float4 f = __ldg(&feat4[i]);
    g_x4[i] = make_float4(f.x * norm, f.y * norm, f.z * norm, f.w * norm);
}

// ---------------------------------------------------------------------------
// 16-byte vector reduction (sm_90+).
// ---------------------------------------------------------------------------
__device__ __forceinline__ void red_add_v4(float4* addr, float4 v)
{
    asm volatile("red.global.add.v4.f32 [%0], {%1, %2, %3, %4};"
                 :: "l"(addr), "f"(v.x), "f"(v.y), "f"(v.z), "f"(v.w)
                 : "memory");
}

// ---------------------------------------------------------------------------
// Kernel 4: scatter.  Per edge: exactly one LDG.128 wavefront (prescaled
// feature line) and one RED.128 wavefront.  16 edges per warp for MLP.
// ---------------------------------------------------------------------------
__global__ void k_scatter(const int*    __restrict__ src,
                          const int*    __restrict__ dst,
                          float4*       __restrict__ out4, int n_edges)
{
    const int Q = EPW / 4;                 // 4 quads
    int gtid = blockIdx.x * blockDim.x + threadIdx.x;
    int warp = gtid >> 5;
    int lane = gtid & 31;
    int grp  = lane >> 3;                  // edge within quad (0..3)
    int c    = lane & 7;                   // float4 chunk     (0..7)
    int base = warp * EPW;
    if (base >= n_edges) return;

    int    s[Q], t[Q];
    float4 v[Q];
    bool   ok[Q];

    #pragma unroll
    for (int q = 0; q < Q; q++) {
        int e = base + q * 4 + grp;
        ok[q] = (e < n_edges);
        int ec = ok[q] ? e : 0;
        s[q] = __ldg(&src[ec]);
        t[q] = __ldg(&dst[ec]);
    }
    #pragma unroll
    for (int q = 0; q < Q; q++)
        v[q] = __ldg(&g_x4[s[q] * (D_FEAT / 4) + c]);
    #pragma unroll
    for (int q = 0; q < Q; q++) {
        if (ok[q])
            red_add_v4(&out4[t[q] * (D_FEAT / 4) + c], v[q]);
    }
}

// ---------------------------------------------------------------------------
// Kernel 5: post-scale by destination norm (float4-vectorized).
// ---------------------------------------------------------------------------
__global__ void k_postscale(float4* __restrict__ out4, int n_nodes)
{
    int i = blockIdx.x * blockDim.x + threadIdx.x;
    int total4 = n_nodes * (D_FEAT / 4);
    if (i >= total4) return;
    float norm = __ldg(&g_norm[i >> 3]);
    float4 o = out4[i];
    out4[i] = make_float4(o.x * norm, o.y * norm, o.z * norm, o.w * norm);
}

extern "C" void kernel_launch(void* const* d_in, const int* in_sizes, int n_in,
                              void* d_out, int out_size)
{
    const float* features = (const float*)d_in[0];
    const int*   src      = (const int*)d_in[1];
    const int*   dst      = (const int*)d_in[2];
    float*       out      = (float*)d_out;

    int n_nodes = in_sizes[0] / D_FEAT;   // 100000
    int n_edges = in_sizes[1];            // 1600000

    const int TPB = 256;
    int total4 = n_nodes * (D_FEAT / 4);

    k_zero<<<(total4 + TPB - 1) / TPB, TPB>>>((float4*)out, n_nodes);

    int n_edges4 = n_edges / 4;
    k_degree<<<(n_edges4 + TPB - 1) / TPB, TPB>>>((const int4*)src, n_edges4);

    k_prescale<<<(total4 + TPB - 1) / TPB, TPB>>>((const float4*)features, n_nodes);

    int warps = (n_edges + EPW - 1) / EPW;
    long long threads = (long long)warps * 32;
    int blocks = (int)((threads + TPB - 1) / TPB);
    k_scatter<<<blocks, TPB>>>(src, dst, (float4*)out, n_edges);

    k_postscale<<<(total4 + TPB - 1) / TPB, TPB>>>((float4*)out, n_nodes);
}